// round 5
// baseline (speedup 1.0000x reference)
#include <cuda_runtime.h>
#include <cuda_bf16.h>
#include <cstdint>

// PolyConv: h = sum_k theta[k] * L_sym^k x, L_sym = I - D^{-1/2} A D^{-1/2}
// N=100000 nodes, E=1600000 edges, F=64 features, k=0..4.

#define NN 100000
#define EE 1600000
#define FF 64

// ---- persistent device scratch (allocation-free rule) ----
__device__ int   g_idx64;                // 1 if edge_index is int64, 0 if int32
__device__ int   g_total;                // CSR allocation cursor
__device__ int   g_cnt[NN];              // in-degree
__device__ int   g_beg[NN];              // row segment start (non-contiguous alloc)
__device__ int   g_cursor[NN];           // fill cursor
__device__ int   g_csr[EE];              // src indices grouped by dst
__device__ float g_dinv[NN];             // rsqrt(max(deg,1))
__device__ float g_feat[2][NN * FF];     // ping-pong feature buffers

// Load edge index element i (0..2E-1) regardless of storage width.
__device__ __forceinline__ int load_idx(const void* __restrict__ ei, int i) {
    if (g_idx64) return (int)((const long long*)ei)[i];
    return ((const int*)ei)[i];
}

// ---------------------------------------------------------------------------
// 0) detect index width: int64 values < 2^31 have zero hi-words; 64 straight
//    zero edge-values in int32 data is impossible for random indices in [0,1e5).
__global__ void k_detect(const int* __restrict__ ei32) {
    if (threadIdx.x == 0) {
        int is64 = 1;
        for (int i = 0; i < 64; i++)
            if (ei32[2 * i + 1] != 0) { is64 = 0; break; }
        g_idx64 = is64;
    }
}

// 1) in-degree histogram over dst (4 edges/thread)
__global__ void k_hist(const void* __restrict__ ei) {
    int base = (blockIdx.x * blockDim.x + threadIdx.x) * 4;
    #pragma unroll
    for (int j = 0; j < 4; j++) {
        int e = base + j;
        if (e < EE) atomicAdd(&g_cnt[load_idx(ei, EE + e)], 1);
    }
}

// 2) segment allocation with warp-aggregated cursor (1 atomic / 32 rows)
__global__ void k_alloc() {
    int i = blockIdx.x * blockDim.x + threadIdx.x;
    int lane = threadIdx.x & 31;
    int c = (i < NN) ? g_cnt[i] : 0;

    // warp-inclusive scan of c
    int inc = c;
    #pragma unroll
    for (int off = 1; off < 32; off <<= 1) {
        int t = __shfl_up_sync(0xffffffffu, inc, off);
        if (lane >= off) inc += t;
    }
    int warpTotal = __shfl_sync(0xffffffffu, inc, 31);
    int base = 0;
    if (lane == 31) base = atomicAdd(&g_total, warpTotal);
    base = __shfl_sync(0xffffffffu, base, 31);

    if (i < NN) {
        int rp = base + inc - c;   // exclusive position
        g_beg[i] = rp;
        g_cursor[i] = rp;
        g_dinv[i] = rsqrtf((float)(c < 1 ? 1 : c));
    }
}

// 3) fill CSR: group src indices by dst
__global__ void k_fill(const void* __restrict__ ei) {
    int base = (blockIdx.x * blockDim.x + threadIdx.x) * 4;
    #pragma unroll
    for (int j = 0; j < 4; j++) {
        int e = base + j;
        if (e < EE) {
            int src = load_idx(ei, e);
            int dst = load_idx(ei, EE + e);
            int p = atomicAdd(&g_cursor[dst], 1);
            g_csr[p] = src;
        }
    }
}

// 4) fused SpMV + epilogue. One warp per row; lane owns features {2*lane, 2*lane+1}.
//    feat_new = feat - dinv[r] * sum_{s in row} feat[s]*dinv[s]
//    FIRST=1:  out = theta0*feat + theta*feat_new
//    FIRST=0:  out += theta*feat_new
template <int FIRST, int WRITE_FOUT>
__global__ void __launch_bounds__(256) k_spmv(const float* __restrict__ fin,
                                              float* __restrict__ fout,
                                              float* __restrict__ out,
                                              float theta0, float theta) {
    int gtid = blockIdx.x * blockDim.x + threadIdx.x;
    int row  = gtid >> 5;
    int lane = gtid & 31;
    if (row >= NN) return;

    int beg = g_beg[row];
    int end = beg + g_cnt[row];

    const float2* __restrict__ f2 = (const float2*)fin;
    float2 acc = make_float2(0.f, 0.f);

    int e = beg;
    // unroll 4: batch index + dinv + row loads to maximize gather MLP
    for (; e + 4 <= end; e += 4) {
        int s0 = g_csr[e];
        int s1 = g_csr[e + 1];
        int s2 = g_csr[e + 2];
        int s3 = g_csr[e + 3];
        float d0 = g_dinv[s0], d1 = g_dinv[s1], d2 = g_dinv[s2], d3 = g_dinv[s3];
        float2 a = __ldg(&f2[s0 * 32 + lane]);
        float2 b = __ldg(&f2[s1 * 32 + lane]);
        float2 cc = __ldg(&f2[s2 * 32 + lane]);
        float2 d = __ldg(&f2[s3 * 32 + lane]);
        acc.x = fmaf(a.x, d0, acc.x); acc.y = fmaf(a.y, d0, acc.y);
        acc.x = fmaf(b.x, d1, acc.x); acc.y = fmaf(b.y, d1, acc.y);
        acc.x = fmaf(cc.x, d2, acc.x); acc.y = fmaf(cc.y, d2, acc.y);
        acc.x = fmaf(d.x, d3, acc.x); acc.y = fmaf(d.y, d3, acc.y);
    }
    for (; e < end; e++) {
        int s0 = g_csr[e];
        float d0 = g_dinv[s0];
        float2 a = __ldg(&f2[s0 * 32 + lane]);
        acc.x = fmaf(a.x, d0, acc.x);
        acc.y = fmaf(a.y, d0, acc.y);
    }

    float dr = g_dinv[row];
    float2 f = __ldg(&f2[row * 32 + lane]);
    float2 n = make_float2(f.x - dr * acc.x, f.y - dr * acc.y);

    if (WRITE_FOUT) {
        ((float2*)fout)[row * 32 + lane] = n;
    }

    float2* o = (float2*)out + row * 32 + lane;
    if (FIRST) {
        *o = make_float2(theta0 * f.x + theta * n.x,
                         theta0 * f.y + theta * n.y);
    } else {
        float2 v = *o;
        *o = make_float2(fmaf(theta, n.x, v.x), fmaf(theta, n.y, v.y));
    }
}

extern "C" void kernel_launch(void* const* d_in, const int* in_sizes, int n_in,
                              void* d_out, int out_size) {
    const float* x   = (const float*)d_in[0];
    const void*  ei  = d_in[1];
    float*       out = (float*)d_out;

    float* feat0; float* feat1;
    cudaGetSymbolAddress((void**)&feat0, g_feat);
    feat1 = feat0 + (size_t)NN * FF;
    int* cnt_ptr;   cudaGetSymbolAddress((void**)&cnt_ptr, g_cnt);
    int* total_ptr; cudaGetSymbolAddress((void**)&total_ptr, g_total);

    const int TB = 256;
    // CSR build
    k_detect<<<1, 32>>>((const int*)ei);
    cudaMemsetAsync(cnt_ptr, 0, NN * sizeof(int));
    cudaMemsetAsync(total_ptr, 0, sizeof(int));
    k_hist<<<(EE / 4 + TB - 1) / TB, TB>>>(ei);
    k_alloc<<<(NN + TB - 1) / TB, TB>>>();
    k_fill<<<(EE / 4 + TB - 1) / TB, TB>>>(ei);

    // 4 fused SpMV iterations (theta = 0.6, -0.4, 0.3, -0.2, 0.1)
    const long long threads = (long long)NN * 32;
    const int blocks = (int)((threads + TB - 1) / TB);
    k_spmv<1, 1><<<blocks, TB>>>(x,     feat0, out, 0.6f, -0.4f);
    k_spmv<0, 1><<<blocks, TB>>>(feat0, feat1, out, 0.0f,  0.3f);
    k_spmv<0, 1><<<blocks, TB>>>(feat1, feat0, out, 0.0f, -0.2f);
    k_spmv<0, 0><<<blocks, TB>>>(feat0, feat1, out, 0.0f,  0.1f);
}

// round 6
// speedup vs baseline: 1.0365x; 1.0365x over previous
#include <cuda_runtime.h>
#include <cuda_bf16.h>
#include <cstdint>

// PolyConv: h = sum_k theta[k] * L_sym^k x, L_sym = I - D^{-1/2} A D^{-1/2}
// N=100000 nodes, E=1600000 edges, F=64 features, k=0..4.

#define NN 100000
#define EE 1600000
#define FF 64

// ---- persistent device scratch (allocation-free rule) ----
__device__ int   g_idx64;                // 1 if edge_index is int64, 0 if int32
__device__ int   g_total;                // CSR allocation cursor
__device__ int   g_cnt[NN];              // in-degree
__device__ int   g_beg[NN];              // row segment start (non-contiguous alloc)
__device__ int   g_rank[EE];             // per-edge rank within its dst row
__device__ int   g_csr[EE];              // src indices grouped by dst
__device__ float g_dinv[NN];             // rsqrt(max(deg,1))
__device__ float g_feat[2][NN * FF];     // ping-pong feature buffers

// Load edge index element i (0..2E-1) regardless of storage width.
__device__ __forceinline__ int load_idx(const void* __restrict__ ei, int i) {
    if (g_idx64) return (int)((const long long*)ei)[i];
    return ((const int*)ei)[i];
}

// ---------------------------------------------------------------------------
// 0) detect index width: int64 values < 2^31 have zero hi-words; 64 straight
//    zero edge-values in int32 data is impossible for random indices in [0,1e5).
__global__ void k_detect(const int* __restrict__ ei32) {
    if (threadIdx.x == 0) {
        int is64 = 1;
        for (int i = 0; i < 64; i++)
            if (ei32[2 * i + 1] != 0) { is64 = 0; break; }
        g_idx64 = is64;
    }
}

// 1) in-degree histogram over dst; also record each edge's rank within its
//    dst row so the fill pass needs no atomics.
__global__ void k_hist(const void* __restrict__ ei) {
    int base = (blockIdx.x * blockDim.x + threadIdx.x) * 4;
    #pragma unroll
    for (int j = 0; j < 4; j++) {
        int e = base + j;
        if (e < EE) {
            int dst = load_idx(ei, EE + e);
            g_rank[e] = atomicAdd(&g_cnt[dst], 1);
        }
    }
}

// 2) segment allocation with warp-aggregated cursor (1 atomic / 32 rows)
__global__ void k_alloc() {
    int i = blockIdx.x * blockDim.x + threadIdx.x;
    int lane = threadIdx.x & 31;
    int c = (i < NN) ? g_cnt[i] : 0;

    // warp-inclusive scan of c
    int inc = c;
    #pragma unroll
    for (int off = 1; off < 32; off <<= 1) {
        int t = __shfl_up_sync(0xffffffffu, inc, off);
        if (lane >= off) inc += t;
    }
    int warpTotal = __shfl_sync(0xffffffffu, inc, 31);
    int base = 0;
    if (lane == 31) base = atomicAdd(&g_total, warpTotal);
    base = __shfl_sync(0xffffffffu, base, 31);

    if (i < NN) {
        g_beg[i] = base + inc - c;   // exclusive position
        g_dinv[i] = rsqrtf((float)(c < 1 ? 1 : c));
    }
}

// 3) fill CSR without atomics: position = beg[dst] + rank[e]
__global__ void k_fill(const void* __restrict__ ei) {
    int base = (blockIdx.x * blockDim.x + threadIdx.x) * 4;
    #pragma unroll
    for (int j = 0; j < 4; j++) {
        int e = base + j;
        if (e < EE) {
            int src = load_idx(ei, e);
            int dst = load_idx(ei, EE + e);
            g_csr[g_beg[dst] + g_rank[e]] = src;
        }
    }
}

// 4) fused SpMV + epilogue. One warp per row; lane owns features {2*lane, 2*lane+1}.
//    feat_new = feat - dinv[r] * sum_{s in row} feat[s]*dinv[s]
//    FIRST=1:  out = theta0*feat + theta*feat_new
//    FIRST=0:  out += theta*feat_new
template <int FIRST, int WRITE_FOUT>
__global__ void __launch_bounds__(256) k_spmv(const float* __restrict__ fin,
                                              float* __restrict__ fout,
                                              float* __restrict__ out,
                                              float theta0, float theta) {
    int gtid = blockIdx.x * blockDim.x + threadIdx.x;
    int row  = gtid >> 5;
    int lane = gtid & 31;
    if (row >= NN) return;

    int beg = g_beg[row];
    int end = beg + g_cnt[row];

    const float2* __restrict__ f2 = (const float2*)fin;
    float2 acc = make_float2(0.f, 0.f);

    int e = beg;
    for (; e + 2 <= end; e += 2) {
        int s0 = g_csr[e];
        int s1 = g_csr[e + 1];
        float d0 = g_dinv[s0];
        float d1 = g_dinv[s1];
        float2 a = __ldg(&f2[s0 * 32 + lane]);
        float2 b = __ldg(&f2[s1 * 32 + lane]);
        acc.x = fmaf(b.x, d1, fmaf(a.x, d0, acc.x));
        acc.y = fmaf(b.y, d1, fmaf(a.y, d0, acc.y));
    }
    if (e < end) {
        int s0 = g_csr[e];
        float d0 = g_dinv[s0];
        float2 a = __ldg(&f2[s0 * 32 + lane]);
        acc.x = fmaf(a.x, d0, acc.x);
        acc.y = fmaf(a.y, d0, acc.y);
    }

    float dr = g_dinv[row];
    float2 f = __ldg(&f2[row * 32 + lane]);
    float2 n = make_float2(f.x - dr * acc.x, f.y - dr * acc.y);

    if (WRITE_FOUT) {
        ((float2*)fout)[row * 32 + lane] = n;
    }

    float2* o = (float2*)out + row * 32 + lane;
    if (FIRST) {
        *o = make_float2(theta0 * f.x + theta * n.x,
                         theta0 * f.y + theta * n.y);
    } else {
        float2 v = *o;
        *o = make_float2(fmaf(theta, n.x, v.x), fmaf(theta, n.y, v.y));
    }
}

extern "C" void kernel_launch(void* const* d_in, const int* in_sizes, int n_in,
                              void* d_out, int out_size) {
    const float* x   = (const float*)d_in[0];
    const void*  ei  = d_in[1];
    float*       out = (float*)d_out;

    float* feat0; float* feat1;
    cudaGetSymbolAddress((void**)&feat0, g_feat);
    feat1 = feat0 + (size_t)NN * FF;
    int* cnt_ptr;   cudaGetSymbolAddress((void**)&cnt_ptr, g_cnt);
    int* total_ptr; cudaGetSymbolAddress((void**)&total_ptr, g_total);

    const int TB = 256;
    // CSR build
    k_detect<<<1, 32>>>((const int*)ei);
    cudaMemsetAsync(cnt_ptr, 0, NN * sizeof(int));
    cudaMemsetAsync(total_ptr, 0, sizeof(int));
    k_hist<<<(EE / 4 + TB - 1) / TB, TB>>>(ei);
    k_alloc<<<(NN + TB - 1) / TB, TB>>>();
    k_fill<<<(EE / 4 + TB - 1) / TB, TB>>>(ei);

    // 4 fused SpMV iterations (theta = 0.6, -0.4, 0.3, -0.2, 0.1)
    const long long threads = (long long)NN * 32;
    const int blocks = (int)((threads + TB - 1) / TB);
    k_spmv<1, 1><<<blocks, TB>>>(x,     feat0, out, 0.6f, -0.4f);
    k_spmv<0, 1><<<blocks, TB>>>(feat0, feat1, out, 0.0f,  0.3f);
    k_spmv<0, 1><<<blocks, TB>>>(feat1, feat0, out, 0.0f, -0.2f);
    k_spmv<0, 0><<<blocks, TB>>>(feat0, feat1, out, 0.0f,  0.1f);
}